// round 14
// baseline (speedup 1.0000x reference)
#include <cuda_runtime.h>
#include <cuda_bf16.h>
#include <math.h>

// ---------------- problem constants ----------------
#define N_TOT   100000
#define N_SEL   5000
#define NB      5
#define BATCH   1000
#define DIMS    256
#define NBUCK   65536
#define BCAP    32
#define CAP     8192
#define T2CUT   279172874u           // 0.065 * 2^32
#define RDIV    1090520u             // ceil(T2CUT/256)
#define NUNITS  (NB * 136)           // 680 symmetric 64x64 tile-pairs
#define KEYS_BLOCKS ((N_TOT + 255) / 256)   // 391, all-resident

// ---------------- scratch ----------------
__device__ unsigned g_keyB[NBUCK * BCAP], g_valB[NBUCK * BCAP];
__device__ unsigned g_cnt[NBUCK], g_start[NBUCK];
__device__ unsigned g_bsum[64];
__device__ unsigned g_bar, g_bar2, g_done;
__device__ unsigned g_sk[4];
__device__ unsigned long long g_cand[CAP];
__device__ unsigned g_ncand;
__device__ unsigned g_qsel[N_SEL];
__device__ unsigned short g_Xb0[(size_t)N_SEL * DIMS];   // bf16 hi split
__device__ unsigned short g_Xb1[(size_t)N_SEL * DIMS];   // bf16 lo split
__device__ float    g_sq[N_SEL];
__device__ int      g_lab[N_SEL];
__device__ unsigned g_ap[N_SEL], g_an[N_SEL];            // d^2 bits

// ---------------- threefry-2x32-20 ----------------
__device__ __forceinline__ void tf2x32(unsigned k0, unsigned k1, unsigned x0, unsigned x1,
                                       unsigned &o0, unsigned &o1) {
    unsigned ks2 = k0 ^ k1 ^ 0x1BD11BDAu;
    x0 += k0; x1 += k1;
#define TFR(r) { x0 += x1; x1 = (x1 << (r)) | (x1 >> (32 - (r))); x1 ^= x0; }
    TFR(13) TFR(15) TFR(26) TFR(6)   x0 += k1;  x1 += ks2 + 1u;
    TFR(17) TFR(29) TFR(16) TFR(24)  x0 += ks2; x1 += k0  + 2u;
    TFR(13) TFR(15) TFR(26) TFR(6)   x0 += k0;  x1 += k1  + 3u;
    TFR(17) TFR(29) TFR(16) TFR(24)  x0 += k1;  x1 += ks2 + 4u;
    TFR(13) TFR(15) TFR(26) TFR(6)   x0 += ks2; x1 += k0  + 5u;
#undef TFR
    o0 = x0; o1 = x1;
}

__device__ __forceinline__ unsigned smem_u32(const void* p) {
    unsigned a;
    asm("{ .reg .u64 t; cvta.to.shared.u64 t, %1; cvt.u32.u64 %0, t; }" : "=r"(a) : "l"(p));
    return a;
}

__device__ __forceinline__ void ldm_x4(unsigned &r0, unsigned &r1, unsigned &r2, unsigned &r3,
                                       unsigned addr) {
    asm volatile("ldmatrix.sync.aligned.m8n8.x4.shared.b16 {%0,%1,%2,%3}, [%4];"
                 : "=r"(r0), "=r"(r1), "=r"(r2), "=r"(r3) : "r"(addr));
}

__device__ __forceinline__ void mma_bf16(float* c, const unsigned* a, const unsigned* b) {
    asm volatile(
        "mma.sync.aligned.m16n8k16.row.col.f32.bf16.bf16.f32 "
        "{%0,%1,%2,%3}, {%4,%5,%6,%7}, {%8,%9}, {%0,%1,%2,%3};"
        : "+f"(c[0]), "+f"(c[1]), "+f"(c[2]), "+f"(c[3])
        : "r"(a[0]), "r"(a[1]), "r"(a[2]), "r"(a[3]), "r"(b[0]), "r"(b[1]));
}

// ---------------- kernels ----------------
// phase 1: zero all state; grid barrier; phase 2: keys + histogram scatter + candidates
__global__ void k_keysinit(const int* uuP) {
    int i = blockIdx.x * blockDim.x + threadIdx.x;

    if (i < NBUCK) g_cnt[i] = 0u;
    if (i < N_SEL) { g_ap[i] = 0u; g_an[i] = 0x7f800000u; }
    if (i < CAP)   g_cand[i] = 0xFFFFFFFFFFFFFFFFull;
    if (i == 0) {
        g_ncand = 0u; g_bar2 = 0u; g_done = 0u;
        unsigned uu = (unsigned)uuP[0];
        unsigned s0, s1, n0, n1, t0, t1;
        tf2x32(0u, uu, 0u, 1u, s0, s1);       // round-0 subkey
        tf2x32(0u, uu, 0u, 0u, n0, n1);       // fold key
        tf2x32(n0, n1, 0u, 1u, t0, t1);       // round-1 subkey
        g_sk[0] = s0; g_sk[1] = s1; g_sk[2] = t0; g_sk[3] = t1;
    }

    __syncthreads();
    if (threadIdx.x == 0) {
        __threadfence();
        atomicAdd(&g_bar, 1u);
        while (atomicAdd(&g_bar, 0u) % (unsigned)KEYS_BLOCKS != 0u) {}
    }
    __syncthreads();

    if (i >= N_TOT) return;
    unsigned s0 = g_sk[0], s1 = g_sk[1], t0 = g_sk[2], t1 = g_sk[3];
    unsigned o0, o1, k1, k2;
    tf2x32(s0, s1, 0u, (unsigned)i, o0, o1); k1 = o0;
    tf2x32(t0, t1, 0u, (unsigned)i, o0, o1); k2 = o0;
    unsigned b = k1 >> 16;
    unsigned slot = atomicAdd(&g_cnt[b], 1u);
    if (slot < BCAP) {
        g_keyB[b * BCAP + slot] = k1;
        g_valB[b * BCAP + slot] = (unsigned)i;
    }
    if (k2 < T2CUT) {
        unsigned p = atomicAdd(&g_ncand, 1u);
        if (p < CAP) g_cand[p] = ((unsigned long long)k2 << 32) | (unsigned)i;
    }
}

// blocks 0..63: grid-wide exclusive scan; block 64: candidate ranking (concurrent)
__global__ void k_scanrank() {
    const int t = threadIdx.x;
    const int bid = blockIdx.x;
    if (bid < 64) {
        __shared__ unsigned s[1024];
        __shared__ unsigned sb[64];
        int g = bid * 1024 + t;
        unsigned v = g_cnt[g];
        s[t] = v;
        __syncthreads();
        for (int off = 1; off < 1024; off <<= 1) {
            unsigned u = (t >= off) ? s[t - off] : 0u;
            __syncthreads();
            s[t] += u;
            __syncthreads();
        }
        unsigned excl = s[t] - v;
        if (t == 1023) g_bsum[bid] = s[t];
        __syncthreads();
        if (t == 0) {
            __threadfence();
            atomicAdd(&g_bar2, 1u);
            while (atomicAdd(&g_bar2, 0u) < 64u) {}
        }
        __syncthreads();
        if (t < 64) sb[t] = g_bsum[t];
        __syncthreads();
        if (t < 64) {
            for (int off = 1; off < 64; off <<= 1) {
                unsigned u = (t >= off) ? sb[t - off] : 0u;
                __syncthreads();
                sb[t] += u;
                __syncthreads();
            }
        } else {
            for (int off = 1; off < 64; off <<= 1) { __syncthreads(); __syncthreads(); }
        }
        unsigned boff = (bid == 0) ? 0u : sb[bid - 1];
        g_start[g] = excl + boff;
    } else {
        extern __shared__ unsigned long long sc[];
        __shared__ unsigned hist[256], hscan[256], curb[256];
        for (int i = t; i < 256; i += 1024) hist[i] = 0u;
        __syncthreads();
        for (int c = t; c < CAP; c += 1024) {
            unsigned k2 = (unsigned)(g_cand[c] >> 32);
            atomicAdd(&hist[min(k2 / RDIV, 255u)], 1u);
        }
        __syncthreads();
        if (t < 256) hscan[t] = hist[t];
        __syncthreads();
        for (int off = 1; off < 256; off <<= 1) {
            unsigned u = (t < 256 && t >= off) ? hscan[t - off] : 0u;
            __syncthreads();
            if (t < 256) hscan[t] += u;
            __syncthreads();
        }
        if (t < 256) curb[t] = hscan[t] - hist[t];
        __syncthreads();
        for (int c = t; c < CAP; c += 1024) {
            unsigned long long val = g_cand[c];
            unsigned b = min((unsigned)(val >> 32) / RDIV, 255u);
            sc[atomicAdd(&curb[b], 1u)] = val;
        }
        __syncthreads();
        for (int c = t; c < CAP; c += 1024) {
            unsigned long long val = sc[c];
            unsigned k2 = (unsigned)(val >> 32);
            if (k2 >= T2CUT) continue;
            unsigned b = min(k2 / RDIV, 255u);
            unsigned s0 = (b == 0) ? 0u : hscan[b - 1];
            unsigned e0 = hscan[b];
            unsigned r = s0;
            for (unsigned j = s0; j < e0; j++) r += (sc[j] < val) ? 1u : 0u;
            if (r < N_SEL) g_qsel[r] = (unsigned)(val & 0xFFFFFFFFull);
        }
    }
}

// split one float4 into hi/lo bf16 packs
__device__ __forceinline__ void bf16_split4(float4 v, unsigned long long &p0, unsigned long long &p1) {
    float xs[4] = {v.x, v.y, v.z, v.w};
    unsigned long long a = 0ull, b = 0ull;
#pragma unroll
    for (int i = 0; i < 4; i++) {
        __nv_bfloat16 h0 = __float2bfloat16(xs[i]);
        float r = xs[i] - __bfloat162float(h0);
        __nv_bfloat16 h1 = __float2bfloat16(r);
        a |= (unsigned long long)__bfloat16_as_ushort(h0) << (16 * i);
        b |= (unsigned long long)__bfloat16_as_ushort(h1) << (16 * i);
    }
    p0 = a; p1 = b;
}

// fused select + gather + bf16 split emission: one warp per final position
__global__ void k_selgather(const float* __restrict__ X, const int* __restrict__ T) {
    int w = (blockIdx.x * blockDim.x + threadIdx.x) >> 5;
    int lane = threadIdx.x & 31;
    if (w >= N_SEL) return;
    unsigned q = g_qsel[w];

    int lo = 0, hi = NBUCK - 1;
    while (lo < hi) {
        int mid = (lo + hi + 1) >> 1;
        if (g_start[mid] <= q) lo = mid; else hi = mid - 1;
    }
    unsigned r = q - g_start[lo];
    unsigned n = min(g_cnt[lo], (unsigned)BCAP);

    unsigned ke = 0xFFFFFFFFu, ve = 0xFFFFFFFFu;
    if (lane < (int)n) { ke = g_keyB[lo * BCAP + lane]; ve = g_valB[lo * BCAP + lane]; }
    unsigned rank = 0;
    for (unsigned f = 0; f < n; f++) {
        unsigned kf = __shfl_sync(0xffffffffu, ke, f);
        unsigned vf = __shfl_sync(0xffffffffu, ve, f);
        if (lane < (int)n && (kf < ke || (kf == ke && vf < ve))) rank++;
    }
    unsigned m = __ballot_sync(0xffffffffu, lane < (int)n && rank == r);
    unsigned src = __shfl_sync(0xffffffffu, ve, __ffs(m) - 1);

    const float4* xr = (const float4*)(X + (size_t)src * DIMS);
    float4 v0 = xr[lane], v1 = xr[lane + 32];
    unsigned long long p0, p1;
    bf16_split4(v0, p0, p1);
    *(unsigned long long*)(g_Xb0 + (size_t)w * DIMS + lane * 4) = p0;
    *(unsigned long long*)(g_Xb1 + (size_t)w * DIMS + lane * 4) = p1;
    bf16_split4(v1, p0, p1);
    *(unsigned long long*)(g_Xb0 + (size_t)w * DIMS + 128 + lane * 4) = p0;
    *(unsigned long long*)(g_Xb1 + (size_t)w * DIMS + 128 + lane * 4) = p1;

    float ss = v0.x * v0.x + v0.y * v0.y + v0.z * v0.z + v0.w * v0.w
             + v1.x * v1.x + v1.y * v1.y + v1.z * v1.z + v1.w * v1.w;
#pragma unroll
    for (int o = 16; o > 0; o >>= 1) ss += __shfl_xor_sync(0xffffffffu, ss, o);
    if (lane == 0) { g_sq[w] = ss; g_lab[w] = T[src]; }
}

// ---------------- mma.sync bf16x2 split-GEMM main + last-CTA reduce ----------------
// 680 symmetric CTAs, 128 threads (2x2 warps), K-chunks of 128, 3-tile smem:
// tiles: [0]=A0, [1]=B0, [2]=SWAP (A1 then B1). 49.4 KB -> 4 CTAs/SM, 1.15 waves.
#define TILE_B   16384
#define SM_SQA   (3 * TILE_B)
#define SM_SQB   (SM_SQA + 256)
#define SM_LABA  (SM_SQB + 256)
#define SM_LABB  (SM_LABA + 256)
#define SMEM_MAIN (SM_LABB + 256)

__global__ void __launch_bounds__(128, 4) k_main(float* __restrict__ out) {
    extern __shared__ char sm[];
    const unsigned base = smem_u32(sm);
    float* sqA = (float*)(sm + SM_SQA);
    float* sqB = (float*)(sm + SM_SQB);
    int* labA = (int*)(sm + SM_LABA);
    int* labB = (int*)(sm + SM_LABB);

    const int tid = threadIdx.x;
    const int lane = tid & 31, wid = tid >> 5;
    const int wrow = (wid >> 1) * 32, wcol = (wid & 1) * 32;

    const int u = blockIdx.x;
    int blk = u / 136;
    int sidx = u - blk * 136;
    int rt = 0, rem = sidx;
    while (rem >= 16 - rt) { rem -= 16 - rt; rt++; }
    int ct = rt + rem;
    const int r0 = rt * 64, c0 = ct * 64;
    const int nrows = min(64, BATCH - r0);
    const int ncols = min(64, BATCH - c0);
    const int rowBase = blk * BATCH + r0;
    const int colBase = blk * BATCH + c0;

    if (tid < 64) {
        sqA[tid]  = (tid < nrows) ? g_sq[rowBase + tid] : 0.f;
        labA[tid] = (tid < nrows) ? g_lab[rowBase + tid] : -1;
        sqB[tid]  = (tid < ncols) ? g_sq[colBase + tid] : 0.f;
        labB[tid] = (tid < ncols) ? g_lab[colBase + tid] : -2;
    }

    float acc[2][4][4];
#pragma unroll
    for (int mi = 0; mi < 2; mi++)
#pragma unroll
        for (int ni = 0; ni < 4; ni++)
#pragma unroll
            for (int e = 0; e < 4; e++) acc[mi][ni][e] = 0.f;

    const int rowA = wrow + (lane & 15);
    const int rowB = wcol + (lane & 7) + ((lane & 16) ? 8 : 0);
    const int chA = (lane >> 4);
    const int chB = ((lane >> 3) & 1);

    // one 8-step segment over (aTile, bTile)
    auto run_seg = [&](unsigned aTile, unsigned bTile) {
#pragma unroll
        for (int s = 0; s < 8; s++) {
            unsigned af[2][4], bf[2][4];
#pragma unroll
            for (int mi = 0; mi < 2; mi++) {
                int rA = rowA + mi * 16;
                unsigned addr = aTile + rA * 256 + ((((2 * s) + chA) ^ (rA & 7)) << 4);
                ldm_x4(af[mi][0], af[mi][1], af[mi][2], af[mi][3], addr);
            }
#pragma unroll
            for (int nj = 0; nj < 2; nj++) {
                int rB = rowB + nj * 16;
                unsigned addr = bTile + rB * 256 + ((((2 * s) + chB) ^ (rB & 7)) << 4);
                ldm_x4(bf[nj][0], bf[nj][1], bf[nj][2], bf[nj][3], addr);
            }
#pragma unroll
            for (int mi = 0; mi < 2; mi++) {
#pragma unroll
                for (int nj = 0; nj < 2; nj++) {
                    mma_bf16(acc[mi][2 * nj],     af[mi], &bf[nj][0]);
                    mma_bf16(acc[mi][2 * nj + 1], af[mi], &bf[nj][2]);
                }
            }
        }
    };

    for (int ch = 0; ch < 2; ch++) {            // 2 K-chunks of 128
        __syncthreads();
        // load A0 -> tile0, B0 -> tile1, A1 -> tile2 (SWAP)
        for (int i = tid; i < 1024; i += 128) {
            int r = i >> 4, c = i & 15;
            unsigned dsto = (unsigned)(r * 256 + ((c ^ (r & 7)) << 4));
            uint4 z = make_uint4(0, 0, 0, 0);
            uint4 a0 = z, a1 = z, b0 = z;
            if (r < nrows) {
                size_t goff = (size_t)(rowBase + r) * DIMS + ch * 128 + c * 8;
                a0 = *(const uint4*)(g_Xb0 + goff);
                a1 = *(const uint4*)(g_Xb1 + goff);
            }
            if (r < ncols) {
                size_t goff = (size_t)(colBase + r) * DIMS + ch * 128 + c * 8;
                b0 = *(const uint4*)(g_Xb0 + goff);
            }
            *(uint4*)(sm + 0 * TILE_B + dsto) = a0;
            *(uint4*)(sm + 1 * TILE_B + dsto) = b0;
            *(uint4*)(sm + 2 * TILE_B + dsto) = a1;
        }
        __syncthreads();
        run_seg(base + 0 * TILE_B, base + 1 * TILE_B);   // A0 * B0
        run_seg(base + 2 * TILE_B, base + 1 * TILE_B);   // A1 * B0
        __syncthreads();
        // reload SWAP = B1
        for (int i = tid; i < 1024; i += 128) {
            int r = i >> 4, c = i & 15;
            unsigned dsto = (unsigned)(r * 256 + ((c ^ (r & 7)) << 4));
            uint4 b1 = make_uint4(0, 0, 0, 0);
            if (r < ncols) {
                size_t goff = (size_t)(colBase + r) * DIMS + ch * 128 + c * 8;
                b1 = *(const uint4*)(g_Xb1 + goff);
            }
            *(uint4*)(sm + 2 * TILE_B + dsto) = b1;
        }
        __syncthreads();
        run_seg(base + 0 * TILE_B, base + 2 * TILE_B);   // A0 * B1
    }

    // ---- epilogue on d^2 ----
    const int g = lane >> 2, qd = lane & 3;
    const float INF = __uint_as_float(0x7f800000u);
    float rP[4], rN[4], cP[8], cN[8];
#pragma unroll
    for (int i = 0; i < 4; i++) { rP[i] = 0.f; rN[i] = INF; }
#pragma unroll
    for (int j = 0; j < 8; j++) { cP[j] = 0.f; cN[j] = INF; }

#pragma unroll
    for (int mi = 0; mi < 2; mi++) {
#pragma unroll
        for (int half = 0; half < 2; half++) {
            int row = wrow + mi * 16 + g + half * 8;
            float sqi = sqA[row];
            int   li  = labA[row];
            bool  vr  = row < nrows;
            int   ri  = mi * 2 + half;
#pragma unroll
            for (int ni = 0; ni < 4; ni++) {
#pragma unroll
                for (int par = 0; par < 2; par++) {
                    int col = wcol + ni * 8 + 2 * qd + par;
                    float gg = acc[mi][ni][half * 2 + par];
                    if (vr && col < ncols) {
                        float d2 = fmaxf(sqi + sqB[col] - 2.f * gg, 1e-12f);
                        int ci = ni * 2 + par;
                        if (li == labB[col]) { rP[ri] = fmaxf(rP[ri], d2); cP[ci] = fmaxf(cP[ci], d2); }
                        else                 { rN[ri] = fminf(rN[ri], d2); cN[ci] = fminf(cN[ci], d2); }
                    }
                }
            }
        }
    }
#pragma unroll
    for (int o = 1; o < 4; o <<= 1) {
#pragma unroll
        for (int i = 0; i < 4; i++) {
            rP[i] = fmaxf(rP[i], __shfl_xor_sync(0xffffffffu, rP[i], o));
            rN[i] = fminf(rN[i], __shfl_xor_sync(0xffffffffu, rN[i], o));
        }
    }
#pragma unroll
    for (int o = 4; o < 32; o <<= 1) {
#pragma unroll
        for (int j = 0; j < 8; j++) {
            cP[j] = fmaxf(cP[j], __shfl_xor_sync(0xffffffffu, cP[j], o));
            cN[j] = fminf(cN[j], __shfl_xor_sync(0xffffffffu, cN[j], o));
        }
    }
    if (qd == 0) {
#pragma unroll
        for (int i = 0; i < 4; i++) {
            int row = wrow + (i >> 1) * 16 + g + (i & 1) * 8;
            if (row < nrows) {
                if (rP[i] > 0.f) atomicMax(&g_ap[rowBase + row], __float_as_uint(rP[i]));
                if (__float_as_uint(rN[i]) != 0x7f800000u)
                    atomicMin(&g_an[rowBase + row], __float_as_uint(rN[i]));
            }
        }
    }
    if (g == 0) {
#pragma unroll
        for (int j = 0; j < 8; j++) {
            int col = wcol + (j >> 1) * 8 + 2 * qd + (j & 1);
            if (col < ncols) {
                if (cP[j] > 0.f) atomicMax(&g_ap[colBase + col], __float_as_uint(cP[j]));
                if (__float_as_uint(cN[j]) != 0x7f800000u)
                    atomicMin(&g_an[colBase + col], __float_as_uint(cN[j]));
            }
        }
    }

    // ---- last CTA reduces ----
    __shared__ unsigned isLast;
    __threadfence();
    __syncthreads();
    if (tid == 0) isLast = (atomicAdd(&g_done, 1u) == (unsigned)(NUNITS - 1)) ? 1u : 0u;
    __syncthreads();
    if (isLast) {
        __threadfence();
        __shared__ float red[128];
        float accr = 0.f;
        for (int i = tid; i < N_SEL; i += 128) {
            float ap = sqrtf(__uint_as_float(__ldcg(&g_ap[i])));
            float an = sqrtf(__uint_as_float(__ldcg(&g_an[i])));
            accr += fmaxf(ap - an + 0.5f, 0.f);
        }
        red[tid] = accr;
        __syncthreads();
        for (int off = 64; off > 0; off >>= 1) {
            if (tid < off) red[tid] += red[tid + off];
            __syncthreads();
        }
        if (tid == 0) out[0] = red[0] * (1.0f / (float)BATCH);
    }
}

// ---------------- launch ----------------
extern "C" void kernel_launch(void* const* d_in, const int* in_sizes, int n_in,
                              void* d_out, int out_size) {
    const float* X  = (const float*)d_in[0];
    const int*   T  = (const int*)d_in[1];
    const int*   UU = (const int*)d_in[2];
    float* out = (float*)d_out;
    (void)in_sizes; (void)n_in; (void)out_size;

    const int SMEM_SR = CAP * 8;   // 64 KB (rank block)

    cudaFuncSetAttribute(k_scanrank, cudaFuncAttributeMaxDynamicSharedMemorySize, SMEM_SR);
    cudaFuncSetAttribute(k_main,     cudaFuncAttributeMaxDynamicSharedMemorySize, SMEM_MAIN);

    k_keysinit<<<KEYS_BLOCKS, 256>>>(UU);
    k_scanrank<<<65, 1024, SMEM_SR>>>();
    k_selgather<<<(N_SEL * 32 + 127) / 128, 128>>>(X, T);
    k_main<<<NUNITS, 128, SMEM_MAIN>>>(out);
}

// round 15
// speedup vs baseline: 1.0039x; 1.0039x over previous
#include <cuda_runtime.h>
#include <cuda_bf16.h>
#include <math.h>

// ---------------- problem constants ----------------
#define N_TOT   100000
#define N_SEL   5000
#define NB      5
#define BATCH   1000
#define DIMS    256
#define NBUCK   65536
#define BCAP    32
#define CAP     8192
#define T2CUT   279172874u           // 0.065 * 2^32
#define RDIV    1090520u             // ceil(T2CUT/256)
#define NUNITS  (NB * 136)           // 680 symmetric 64x64 tile-pairs
#define KEYS_BLOCKS ((N_TOT + 255) / 256)   // 391, all-resident

// ---------------- scratch ----------------
__device__ unsigned g_keyB[NBUCK * BCAP], g_valB[NBUCK * BCAP];
__device__ unsigned g_cnt[NBUCK], g_start[NBUCK];
__device__ unsigned g_bsum[64];
__device__ unsigned g_bar, g_bar2, g_done;
__device__ unsigned g_sk[4];
__device__ unsigned long long g_cand[CAP];
__device__ unsigned g_ncand;
__device__ unsigned g_qsel[N_SEL];
__device__ unsigned short g_Xb0[(size_t)N_SEL * DIMS];   // bf16 hi split
__device__ unsigned short g_Xb1[(size_t)N_SEL * DIMS];   // bf16 lo split
__device__ float    g_sq[N_SEL];
__device__ int      g_lab[N_SEL];
__device__ unsigned g_ap[N_SEL], g_an[N_SEL];            // d^2 bits

// ---------------- threefry-2x32-20 ----------------
__device__ __forceinline__ void tf2x32(unsigned k0, unsigned k1, unsigned x0, unsigned x1,
                                       unsigned &o0, unsigned &o1) {
    unsigned ks2 = k0 ^ k1 ^ 0x1BD11BDAu;
    x0 += k0; x1 += k1;
#define TFR(r) { x0 += x1; x1 = (x1 << (r)) | (x1 >> (32 - (r))); x1 ^= x0; }
    TFR(13) TFR(15) TFR(26) TFR(6)   x0 += k1;  x1 += ks2 + 1u;
    TFR(17) TFR(29) TFR(16) TFR(24)  x0 += ks2; x1 += k0  + 2u;
    TFR(13) TFR(15) TFR(26) TFR(6)   x0 += k0;  x1 += k1  + 3u;
    TFR(17) TFR(29) TFR(16) TFR(24)  x0 += k1;  x1 += ks2 + 4u;
    TFR(13) TFR(15) TFR(26) TFR(6)   x0 += ks2; x1 += k0  + 5u;
#undef TFR
    o0 = x0; o1 = x1;
}

__device__ __forceinline__ unsigned smem_u32(const void* p) {
    unsigned a;
    asm("{ .reg .u64 t; cvta.to.shared.u64 t, %1; cvt.u32.u64 %0, t; }" : "=r"(a) : "l"(p));
    return a;
}

__device__ __forceinline__ void ldm_x4(unsigned &r0, unsigned &r1, unsigned &r2, unsigned &r3,
                                       unsigned addr) {
    asm volatile("ldmatrix.sync.aligned.m8n8.x4.shared.b16 {%0,%1,%2,%3}, [%4];"
                 : "=r"(r0), "=r"(r1), "=r"(r2), "=r"(r3) : "r"(addr));
}

__device__ __forceinline__ void mma_bf16(float* c, const unsigned* a, const unsigned* b) {
    asm volatile(
        "mma.sync.aligned.m16n8k16.row.col.f32.bf16.bf16.f32 "
        "{%0,%1,%2,%3}, {%4,%5,%6,%7}, {%8,%9}, {%0,%1,%2,%3};"
        : "+f"(c[0]), "+f"(c[1]), "+f"(c[2]), "+f"(c[3])
        : "r"(a[0]), "r"(a[1]), "r"(a[2]), "r"(a[3]), "r"(b[0]), "r"(b[1]));
}

// ---------------- kernels ----------------
// phase 1: zero all state; grid barrier; phase 2: keys + histogram scatter + candidates
__global__ void k_keysinit(const int* uuP) {
    int i = blockIdx.x * blockDim.x + threadIdx.x;

    if (i < NBUCK) g_cnt[i] = 0u;
    if (i < N_SEL) { g_ap[i] = 0u; g_an[i] = 0x7f800000u; }
    if (i < CAP)   g_cand[i] = 0xFFFFFFFFFFFFFFFFull;
    if (i == 0) {
        g_ncand = 0u; g_bar2 = 0u; g_done = 0u;
        unsigned uu = (unsigned)uuP[0];
        unsigned s0, s1, n0, n1, t0, t1;
        tf2x32(0u, uu, 0u, 1u, s0, s1);       // round-0 subkey
        tf2x32(0u, uu, 0u, 0u, n0, n1);       // fold key
        tf2x32(n0, n1, 0u, 1u, t0, t1);       // round-1 subkey
        g_sk[0] = s0; g_sk[1] = s1; g_sk[2] = t0; g_sk[3] = t1;
    }

    __syncthreads();
    if (threadIdx.x == 0) {
        __threadfence();
        atomicAdd(&g_bar, 1u);
        while (atomicAdd(&g_bar, 0u) % (unsigned)KEYS_BLOCKS != 0u) {}
    }
    __syncthreads();

    if (i >= N_TOT) return;
    unsigned s0 = g_sk[0], s1 = g_sk[1], t0 = g_sk[2], t1 = g_sk[3];
    unsigned o0, o1, k1, k2;
    tf2x32(s0, s1, 0u, (unsigned)i, o0, o1); k1 = o0;
    tf2x32(t0, t1, 0u, (unsigned)i, o0, o1); k2 = o0;
    unsigned b = k1 >> 16;
    unsigned slot = atomicAdd(&g_cnt[b], 1u);
    if (slot < BCAP) {
        g_keyB[b * BCAP + slot] = k1;
        g_valB[b * BCAP + slot] = (unsigned)i;
    }
    if (k2 < T2CUT) {
        unsigned p = atomicAdd(&g_ncand, 1u);
        if (p < CAP) g_cand[p] = ((unsigned long long)k2 << 32) | (unsigned)i;
    }
}

// blocks 0..63: grid-wide exclusive scan; block 64: candidate ranking (concurrent)
__global__ void k_scanrank() {
    const int t = threadIdx.x;
    const int bid = blockIdx.x;
    if (bid < 64) {
        __shared__ unsigned s[1024];
        __shared__ unsigned sb[64];
        int g = bid * 1024 + t;
        unsigned v = g_cnt[g];
        s[t] = v;
        __syncthreads();
        for (int off = 1; off < 1024; off <<= 1) {
            unsigned u = (t >= off) ? s[t - off] : 0u;
            __syncthreads();
            s[t] += u;
            __syncthreads();
        }
        unsigned excl = s[t] - v;
        if (t == 1023) g_bsum[bid] = s[t];
        __syncthreads();
        if (t == 0) {
            __threadfence();
            atomicAdd(&g_bar2, 1u);
            while (atomicAdd(&g_bar2, 0u) < 64u) {}
        }
        __syncthreads();
        if (t < 64) sb[t] = g_bsum[t];
        __syncthreads();
        if (t < 64) {
            for (int off = 1; off < 64; off <<= 1) {
                unsigned u = (t >= off) ? sb[t - off] : 0u;
                __syncthreads();
                sb[t] += u;
                __syncthreads();
            }
        } else {
            for (int off = 1; off < 64; off <<= 1) { __syncthreads(); __syncthreads(); }
        }
        unsigned boff = (bid == 0) ? 0u : sb[bid - 1];
        g_start[g] = excl + boff;
    } else {
        extern __shared__ unsigned long long sc[];
        __shared__ unsigned hist[256], hscan[256], curb[256];
        for (int i = t; i < 256; i += 1024) hist[i] = 0u;
        __syncthreads();
        for (int c = t; c < CAP; c += 1024) {
            unsigned k2 = (unsigned)(g_cand[c] >> 32);
            atomicAdd(&hist[min(k2 / RDIV, 255u)], 1u);
        }
        __syncthreads();
        if (t < 256) hscan[t] = hist[t];
        __syncthreads();
        for (int off = 1; off < 256; off <<= 1) {
            unsigned u = (t < 256 && t >= off) ? hscan[t - off] : 0u;
            __syncthreads();
            if (t < 256) hscan[t] += u;
            __syncthreads();
        }
        if (t < 256) curb[t] = hscan[t] - hist[t];
        __syncthreads();
        for (int c = t; c < CAP; c += 1024) {
            unsigned long long val = g_cand[c];
            unsigned b = min((unsigned)(val >> 32) / RDIV, 255u);
            sc[atomicAdd(&curb[b], 1u)] = val;
        }
        __syncthreads();
        for (int c = t; c < CAP; c += 1024) {
            unsigned long long val = sc[c];
            unsigned k2 = (unsigned)(val >> 32);
            if (k2 >= T2CUT) continue;
            unsigned b = min(k2 / RDIV, 255u);
            unsigned s0 = (b == 0) ? 0u : hscan[b - 1];
            unsigned e0 = hscan[b];
            unsigned r = s0;
            for (unsigned j = s0; j < e0; j++) r += (sc[j] < val) ? 1u : 0u;
            if (r < N_SEL) g_qsel[r] = (unsigned)(val & 0xFFFFFFFFull);
        }
    }
}

// split one float4 into hi/lo bf16 packs
__device__ __forceinline__ void bf16_split4(float4 v, unsigned long long &p0, unsigned long long &p1) {
    float xs[4] = {v.x, v.y, v.z, v.w};
    unsigned long long a = 0ull, b = 0ull;
#pragma unroll
    for (int i = 0; i < 4; i++) {
        __nv_bfloat16 h0 = __float2bfloat16(xs[i]);
        float r = xs[i] - __bfloat162float(h0);
        __nv_bfloat16 h1 = __float2bfloat16(r);
        a |= (unsigned long long)__bfloat16_as_ushort(h0) << (16 * i);
        b |= (unsigned long long)__bfloat16_as_ushort(h1) << (16 * i);
    }
    p0 = a; p1 = b;
}

// fused select + gather + bf16 split emission: one warp per final position
__global__ void k_selgather(const float* __restrict__ X, const int* __restrict__ T) {
    int w = (blockIdx.x * blockDim.x + threadIdx.x) >> 5;
    int lane = threadIdx.x & 31;
    if (w >= N_SEL) return;
    unsigned q = g_qsel[w];

    int lo = 0, hi = NBUCK - 1;
    while (lo < hi) {
        int mid = (lo + hi + 1) >> 1;
        if (g_start[mid] <= q) lo = mid; else hi = mid - 1;
    }
    unsigned r = q - g_start[lo];
    unsigned n = min(g_cnt[lo], (unsigned)BCAP);

    unsigned ke = 0xFFFFFFFFu, ve = 0xFFFFFFFFu;
    if (lane < (int)n) { ke = g_keyB[lo * BCAP + lane]; ve = g_valB[lo * BCAP + lane]; }
    unsigned rank = 0;
    for (unsigned f = 0; f < n; f++) {
        unsigned kf = __shfl_sync(0xffffffffu, ke, f);
        unsigned vf = __shfl_sync(0xffffffffu, ve, f);
        if (lane < (int)n && (kf < ke || (kf == ke && vf < ve))) rank++;
    }
    unsigned m = __ballot_sync(0xffffffffu, lane < (int)n && rank == r);
    unsigned src = __shfl_sync(0xffffffffu, ve, __ffs(m) - 1);

    const float4* xr = (const float4*)(X + (size_t)src * DIMS);
    float4 v0 = xr[lane], v1 = xr[lane + 32];
    unsigned long long p0, p1;
    bf16_split4(v0, p0, p1);
    *(unsigned long long*)(g_Xb0 + (size_t)w * DIMS + lane * 4) = p0;
    *(unsigned long long*)(g_Xb1 + (size_t)w * DIMS + lane * 4) = p1;
    bf16_split4(v1, p0, p1);
    *(unsigned long long*)(g_Xb0 + (size_t)w * DIMS + 128 + lane * 4) = p0;
    *(unsigned long long*)(g_Xb1 + (size_t)w * DIMS + 128 + lane * 4) = p1;

    float ss = v0.x * v0.x + v0.y * v0.y + v0.z * v0.z + v0.w * v0.w
             + v1.x * v1.x + v1.y * v1.y + v1.z * v1.z + v1.w * v1.w;
#pragma unroll
    for (int o = 16; o > 0; o >>= 1) ss += __shfl_xor_sync(0xffffffffu, ss, o);
    if (lane == 0) { g_sq[w] = ss; g_lab[w] = T[src]; }
}

// ---------------- mma.sync bf16x2 split-GEMM main (R12 config) + last-CTA reduce ----
// 680 symmetric CTAs, 128 threads (2x2 warps, 32x32 warp tiles), K-chunks of 128
// smem: A0,A1,B0,B1 (64 rows x 128 bf16 = 16KB each) + sq/lab = 66560 B -> 3 CTAs/SM
#define TILE_B   16384
#define SM_SQA   (4 * TILE_B)
#define SM_SQB   (SM_SQA + 256)
#define SM_LABA  (SM_SQB + 256)
#define SM_LABB  (SM_LABA + 256)
#define SMEM_MAIN (SM_LABB + 256)

__global__ void __launch_bounds__(128, 3) k_main(float* __restrict__ out) {
    extern __shared__ char sm[];
    const unsigned base = smem_u32(sm);
    float* sqA = (float*)(sm + SM_SQA);
    float* sqB = (float*)(sm + SM_SQB);
    int* labA = (int*)(sm + SM_LABA);
    int* labB = (int*)(sm + SM_LABB);

    const int tid = threadIdx.x;
    const int lane = tid & 31, wid = tid >> 5;
    const int wrow = (wid >> 1) * 32, wcol = (wid & 1) * 32;

    const int u = blockIdx.x;
    int blk = u / 136;
    int sidx = u - blk * 136;
    int rt = 0, rem = sidx;
    while (rem >= 16 - rt) { rem -= 16 - rt; rt++; }
    int ct = rt + rem;
    const int r0 = rt * 64, c0 = ct * 64;
    const int nrows = min(64, BATCH - r0);
    const int ncols = min(64, BATCH - c0);
    const int rowBase = blk * BATCH + r0;
    const int colBase = blk * BATCH + c0;

    if (tid < 64) {
        sqA[tid]  = (tid < nrows) ? g_sq[rowBase + tid] : 0.f;
        labA[tid] = (tid < nrows) ? g_lab[rowBase + tid] : -1;
        sqB[tid]  = (tid < ncols) ? g_sq[colBase + tid] : 0.f;
        labB[tid] = (tid < ncols) ? g_lab[colBase + tid] : -2;
    }

    float acc[2][4][4];
#pragma unroll
    for (int mi = 0; mi < 2; mi++)
#pragma unroll
        for (int ni = 0; ni < 4; ni++)
#pragma unroll
            for (int e = 0; e < 4; e++) acc[mi][ni][e] = 0.f;

    const int rowA = wrow + (lane & 15);
    const int rowB = wcol + (lane & 7) + ((lane & 16) ? 8 : 0);
    const int chA = (lane >> 4);
    const int chB = ((lane >> 3) & 1);

    for (int ch = 0; ch < 2; ch++) {
        __syncthreads();
        // load 4 tiles (16B chunk per thread-iter), XOR swizzle: chunk16 ^= row&7
        for (int i = tid; i < 64 * 16; i += 128) {
            int r = i >> 4, c = i & 15;
            unsigned dsto = (unsigned)(r * 256 + ((c ^ (r & 7)) << 4));
            uint4 z = make_uint4(0, 0, 0, 0);
            uint4 a0 = z, a1 = z, b0 = z, b1 = z;
            if (r < nrows) {
                size_t goff = (size_t)(rowBase + r) * DIMS + ch * 128 + c * 8;
                a0 = *(const uint4*)(g_Xb0 + goff);
                a1 = *(const uint4*)(g_Xb1 + goff);
            }
            if (r < ncols) {
                size_t goff = (size_t)(colBase + r) * DIMS + ch * 128 + c * 8;
                b0 = *(const uint4*)(g_Xb0 + goff);
                b1 = *(const uint4*)(g_Xb1 + goff);
            }
            *(uint4*)(sm + 0 * TILE_B + dsto) = a0;
            *(uint4*)(sm + 1 * TILE_B + dsto) = a1;
            *(uint4*)(sm + 2 * TILE_B + dsto) = b0;
            *(uint4*)(sm + 3 * TILE_B + dsto) = b1;
        }
        __syncthreads();

#pragma unroll 1
        for (int seg = 0; seg < 3; seg++) {
            const unsigned aTile = base + ((seg == 1) ? 1u : 0u) * TILE_B;
            const unsigned bTile = base + ((seg == 2) ? 3u : 2u) * TILE_B;
#pragma unroll
            for (int s = 0; s < 8; s++) {
                unsigned af[2][4], bf[2][4];
#pragma unroll
                for (int mi = 0; mi < 2; mi++) {
                    int rA = rowA + mi * 16;
                    unsigned addr = aTile + rA * 256 + ((((2 * s) + chA) ^ (rA & 7)) << 4);
                    ldm_x4(af[mi][0], af[mi][1], af[mi][2], af[mi][3], addr);
                }
#pragma unroll
                for (int nj = 0; nj < 2; nj++) {
                    int rB = rowB + nj * 16;
                    unsigned addr = bTile + rB * 256 + ((((2 * s) + chB) ^ (rB & 7)) << 4);
                    ldm_x4(bf[nj][0], bf[nj][1], bf[nj][2], bf[nj][3], addr);
                }
#pragma unroll
                for (int mi = 0; mi < 2; mi++) {
#pragma unroll
                    for (int nj = 0; nj < 2; nj++) {
                        mma_bf16(acc[mi][2 * nj],     af[mi], &bf[nj][0]);
                        mma_bf16(acc[mi][2 * nj + 1], af[mi], &bf[nj][2]);
                    }
                }
            }
        }
    }

    // ---- epilogue on d^2 ----
    const int g = lane >> 2, qd = lane & 3;
    const float INF = __uint_as_float(0x7f800000u);
    float rP[4], rN[4], cP[8], cN[8];
#pragma unroll
    for (int i = 0; i < 4; i++) { rP[i] = 0.f; rN[i] = INF; }
#pragma unroll
    for (int j = 0; j < 8; j++) { cP[j] = 0.f; cN[j] = INF; }

#pragma unroll
    for (int mi = 0; mi < 2; mi++) {
#pragma unroll
        for (int half = 0; half < 2; half++) {
            int row = wrow + mi * 16 + g + half * 8;
            float sqi = sqA[row];
            int   li  = labA[row];
            bool  vr  = row < nrows;
            int   ri  = mi * 2 + half;
#pragma unroll
            for (int ni = 0; ni < 4; ni++) {
#pragma unroll
                for (int par = 0; par < 2; par++) {
                    int col = wcol + ni * 8 + 2 * qd + par;
                    float gg = acc[mi][ni][half * 2 + par];
                    if (vr && col < ncols) {
                        float d2 = fmaxf(sqi + sqB[col] - 2.f * gg, 1e-12f);
                        int ci = ni * 2 + par;
                        if (li == labB[col]) { rP[ri] = fmaxf(rP[ri], d2); cP[ci] = fmaxf(cP[ci], d2); }
                        else                 { rN[ri] = fminf(rN[ri], d2); cN[ci] = fminf(cN[ci], d2); }
                    }
                }
            }
        }
    }
#pragma unroll
    for (int o = 1; o < 4; o <<= 1) {
#pragma unroll
        for (int i = 0; i < 4; i++) {
            rP[i] = fmaxf(rP[i], __shfl_xor_sync(0xffffffffu, rP[i], o));
            rN[i] = fminf(rN[i], __shfl_xor_sync(0xffffffffu, rN[i], o));
        }
    }
#pragma unroll
    for (int o = 4; o < 32; o <<= 1) {
#pragma unroll
        for (int j = 0; j < 8; j++) {
            cP[j] = fmaxf(cP[j], __shfl_xor_sync(0xffffffffu, cP[j], o));
            cN[j] = fminf(cN[j], __shfl_xor_sync(0xffffffffu, cN[j], o));
        }
    }
    if (qd == 0) {
#pragma unroll
        for (int i = 0; i < 4; i++) {
            int row = wrow + (i >> 1) * 16 + g + (i & 1) * 8;
            if (row < nrows) {
                if (rP[i] > 0.f) atomicMax(&g_ap[rowBase + row], __float_as_uint(rP[i]));
                if (__float_as_uint(rN[i]) != 0x7f800000u)
                    atomicMin(&g_an[rowBase + row], __float_as_uint(rN[i]));
            }
        }
    }
    if (g == 0) {
#pragma unroll
        for (int j = 0; j < 8; j++) {
            int col = wcol + (j >> 1) * 8 + 2 * qd + (j & 1);
            if (col < ncols) {
                if (cP[j] > 0.f) atomicMax(&g_ap[colBase + col], __float_as_uint(cP[j]));
                if (__float_as_uint(cN[j]) != 0x7f800000u)
                    atomicMin(&g_an[colBase + col], __float_as_uint(cN[j]));
            }
        }
    }

    // ---- last CTA reduces ----
    __shared__ unsigned isLast;
    __threadfence();
    __syncthreads();
    if (tid == 0) isLast = (atomicAdd(&g_done, 1u) == (unsigned)(NUNITS - 1)) ? 1u : 0u;
    __syncthreads();
    if (isLast) {
        __threadfence();
        __shared__ float red[128];
        float accr = 0.f;
        for (int i = tid; i < N_SEL; i += 128) {
            float ap = sqrtf(__uint_as_float(__ldcg(&g_ap[i])));
            float an = sqrtf(__uint_as_float(__ldcg(&g_an[i])));
            accr += fmaxf(ap - an + 0.5f, 0.f);
        }
        red[tid] = accr;
        __syncthreads();
        for (int off = 64; off > 0; off >>= 1) {
            if (tid < off) red[tid] += red[tid + off];
            __syncthreads();
        }
        if (tid == 0) out[0] = red[0] * (1.0f / (float)BATCH);
    }
}

// ---------------- launch ----------------
extern "C" void kernel_launch(void* const* d_in, const int* in_sizes, int n_in,
                              void* d_out, int out_size) {
    const float* X  = (const float*)d_in[0];
    const int*   T  = (const int*)d_in[1];
    const int*   UU = (const int*)d_in[2];
    float* out = (float*)d_out;
    (void)in_sizes; (void)n_in; (void)out_size;

    const int SMEM_SR = CAP * 8;   // 64 KB (rank block)

    cudaFuncSetAttribute(k_scanrank, cudaFuncAttributeMaxDynamicSharedMemorySize, SMEM_SR);
    cudaFuncSetAttribute(k_main,     cudaFuncAttributeMaxDynamicSharedMemorySize, SMEM_MAIN);

    k_keysinit<<<KEYS_BLOCKS, 256>>>(UU);
    k_scanrank<<<65, 1024, SMEM_SR>>>();
    k_selgather<<<(N_SEL * 32 + 127) / 128, 128>>>(X, T);
    k_main<<<NUNITS, 128, SMEM_MAIN>>>(out);
}

// round 16
// speedup vs baseline: 1.2984x; 1.2934x over previous
#include <cuda_runtime.h>
#include <cuda_bf16.h>
#include <math.h>

// ---------------- problem constants ----------------
#define N_TOT   100000
#define N_SEL   5000
#define NB      5
#define BATCH   1000
#define DIMS    256
#define NBUCK   65536
#define BCAP    32
#define CAP     8192
#define T2CUT   279172874u           // 0.065 * 2^32
#define RDIV    1090520u             // ceil(T2CUT/256)
#define NUNITS  (NB * 136)           // 680 symmetric 64x64 tile-pairs
#define KEYS_BLOCKS ((N_TOT + 255) / 256)   // 391, all-resident

// ---------------- scratch ----------------
__device__ unsigned g_keyB[NBUCK * BCAP], g_valB[NBUCK * BCAP];
__device__ unsigned g_cnt[NBUCK], g_start[NBUCK];
__device__ unsigned g_bsum[64];
__device__ unsigned g_bar, g_bar2;
__device__ unsigned g_sk[4];
__device__ unsigned long long g_cand[CAP];
__device__ unsigned g_ncand;
__device__ unsigned g_qsel[N_SEL];
__device__ unsigned short g_Xb0[(size_t)N_SEL * DIMS];   // bf16 hi split
__device__ unsigned short g_Xb1[(size_t)N_SEL * DIMS];   // bf16 lo split
__device__ float    g_sq[N_SEL];
__device__ int      g_lab[N_SEL];
__device__ unsigned g_ap[N_SEL], g_an[N_SEL];            // d^2 bits

// ---------------- threefry-2x32-20 ----------------
__device__ __forceinline__ void tf2x32(unsigned k0, unsigned k1, unsigned x0, unsigned x1,
                                       unsigned &o0, unsigned &o1) {
    unsigned ks2 = k0 ^ k1 ^ 0x1BD11BDAu;
    x0 += k0; x1 += k1;
#define TFR(r) { x0 += x1; x1 = (x1 << (r)) | (x1 >> (32 - (r))); x1 ^= x0; }
    TFR(13) TFR(15) TFR(26) TFR(6)   x0 += k1;  x1 += ks2 + 1u;
    TFR(17) TFR(29) TFR(16) TFR(24)  x0 += ks2; x1 += k0  + 2u;
    TFR(13) TFR(15) TFR(26) TFR(6)   x0 += k0;  x1 += k1  + 3u;
    TFR(17) TFR(29) TFR(16) TFR(24)  x0 += k1;  x1 += ks2 + 4u;
    TFR(13) TFR(15) TFR(26) TFR(6)   x0 += ks2; x1 += k0  + 5u;
#undef TFR
    o0 = x0; o1 = x1;
}

__device__ __forceinline__ unsigned smem_u32(const void* p) {
    unsigned a;
    asm("{ .reg .u64 t; cvta.to.shared.u64 t, %1; cvt.u32.u64 %0, t; }" : "=r"(a) : "l"(p));
    return a;
}

__device__ __forceinline__ void ldm_x4(unsigned &r0, unsigned &r1, unsigned &r2, unsigned &r3,
                                       unsigned addr) {
    asm volatile("ldmatrix.sync.aligned.m8n8.x4.shared.b16 {%0,%1,%2,%3}, [%4];"
                 : "=r"(r0), "=r"(r1), "=r"(r2), "=r"(r3) : "r"(addr));
}

__device__ __forceinline__ void mma_bf16(float* c, const unsigned* a, const unsigned* b) {
    asm volatile(
        "mma.sync.aligned.m16n8k16.row.col.f32.bf16.bf16.f32 "
        "{%0,%1,%2,%3}, {%4,%5,%6,%7}, {%8,%9}, {%0,%1,%2,%3};"
        : "+f"(c[0]), "+f"(c[1]), "+f"(c[2]), "+f"(c[3])
        : "r"(a[0]), "r"(a[1]), "r"(a[2]), "r"(a[3]), "r"(b[0]), "r"(b[1]));
}

// ---------------- kernels ----------------
// phase 1: zero all state; grid barrier; phase 2: keys + histogram scatter + candidates
__global__ void k_keysinit(const int* uuP) {
    int i = blockIdx.x * blockDim.x + threadIdx.x;

    if (i < NBUCK) g_cnt[i] = 0u;
    if (i < N_SEL) { g_ap[i] = 0u; g_an[i] = 0x7f800000u; }
    if (i < CAP)   g_cand[i] = 0xFFFFFFFFFFFFFFFFull;
    if (i == 0) {
        g_ncand = 0u; g_bar2 = 0u;
        unsigned uu = (unsigned)uuP[0];
        unsigned s0, s1, n0, n1, t0, t1;
        tf2x32(0u, uu, 0u, 1u, s0, s1);       // round-0 subkey
        tf2x32(0u, uu, 0u, 0u, n0, n1);       // fold key
        tf2x32(n0, n1, 0u, 1u, t0, t1);       // round-1 subkey
        g_sk[0] = s0; g_sk[1] = s1; g_sk[2] = t0; g_sk[3] = t1;
    }

    __syncthreads();
    if (threadIdx.x == 0) {
        __threadfence();
        atomicAdd(&g_bar, 1u);
        while (atomicAdd(&g_bar, 0u) % (unsigned)KEYS_BLOCKS != 0u) {}
    }
    __syncthreads();

    if (i >= N_TOT) return;
    unsigned s0 = g_sk[0], s1 = g_sk[1], t0 = g_sk[2], t1 = g_sk[3];
    unsigned o0, o1, k1, k2;
    tf2x32(s0, s1, 0u, (unsigned)i, o0, o1); k1 = o0;
    tf2x32(t0, t1, 0u, (unsigned)i, o0, o1); k2 = o0;
    unsigned b = k1 >> 16;
    unsigned slot = atomicAdd(&g_cnt[b], 1u);
    if (slot < BCAP) {
        g_keyB[b * BCAP + slot] = k1;
        g_valB[b * BCAP + slot] = (unsigned)i;
    }
    if (k2 < T2CUT) {
        unsigned p = atomicAdd(&g_ncand, 1u);
        if (p < CAP) g_cand[p] = ((unsigned long long)k2 << 32) | (unsigned)i;
    }
}

// blocks 0..63: grid-wide exclusive scan; block 64: candidate ranking (concurrent)
__global__ void k_scanrank() {
    const int t = threadIdx.x;
    const int bid = blockIdx.x;
    if (bid < 64) {
        __shared__ unsigned s[1024];
        __shared__ unsigned sb[64];
        int g = bid * 1024 + t;
        unsigned v = g_cnt[g];
        s[t] = v;
        __syncthreads();
        for (int off = 1; off < 1024; off <<= 1) {
            unsigned u = (t >= off) ? s[t - off] : 0u;
            __syncthreads();
            s[t] += u;
            __syncthreads();
        }
        unsigned excl = s[t] - v;
        if (t == 1023) g_bsum[bid] = s[t];
        __syncthreads();
        if (t == 0) {
            __threadfence();
            atomicAdd(&g_bar2, 1u);
            while (atomicAdd(&g_bar2, 0u) < 64u) {}
        }
        __syncthreads();
        if (t < 64) sb[t] = g_bsum[t];
        __syncthreads();
        if (t < 64) {
            for (int off = 1; off < 64; off <<= 1) {
                unsigned u = (t >= off) ? sb[t - off] : 0u;
                __syncthreads();
                sb[t] += u;
                __syncthreads();
            }
        } else {
            for (int off = 1; off < 64; off <<= 1) { __syncthreads(); __syncthreads(); }
        }
        unsigned boff = (bid == 0) ? 0u : sb[bid - 1];
        g_start[g] = excl + boff;
    } else {
        extern __shared__ unsigned long long sc[];
        __shared__ unsigned hist[256], hscan[256], curb[256];
        for (int i = t; i < 256; i += 1024) hist[i] = 0u;
        __syncthreads();
        for (int c = t; c < CAP; c += 1024) {
            unsigned k2 = (unsigned)(g_cand[c] >> 32);
            atomicAdd(&hist[min(k2 / RDIV, 255u)], 1u);
        }
        __syncthreads();
        if (t < 256) hscan[t] = hist[t];
        __syncthreads();
        for (int off = 1; off < 256; off <<= 1) {
            unsigned u = (t < 256 && t >= off) ? hscan[t - off] : 0u;
            __syncthreads();
            if (t < 256) hscan[t] += u;
            __syncthreads();
        }
        if (t < 256) curb[t] = hscan[t] - hist[t];
        __syncthreads();
        for (int c = t; c < CAP; c += 1024) {
            unsigned long long val = g_cand[c];
            unsigned b = min((unsigned)(val >> 32) / RDIV, 255u);
            sc[atomicAdd(&curb[b], 1u)] = val;
        }
        __syncthreads();
        for (int c = t; c < CAP; c += 1024) {
            unsigned long long val = sc[c];
            unsigned k2 = (unsigned)(val >> 32);
            if (k2 >= T2CUT) continue;
            unsigned b = min(k2 / RDIV, 255u);
            unsigned s0 = (b == 0) ? 0u : hscan[b - 1];
            unsigned e0 = hscan[b];
            unsigned r = s0;
            for (unsigned j = s0; j < e0; j++) r += (sc[j] < val) ? 1u : 0u;
            if (r < N_SEL) g_qsel[r] = (unsigned)(val & 0xFFFFFFFFull);
        }
    }
}

// split one float4 into hi/lo bf16 packs
__device__ __forceinline__ void bf16_split4(float4 v, unsigned long long &p0, unsigned long long &p1) {
    float xs[4] = {v.x, v.y, v.z, v.w};
    unsigned long long a = 0ull, b = 0ull;
#pragma unroll
    for (int i = 0; i < 4; i++) {
        __nv_bfloat16 h0 = __float2bfloat16(xs[i]);
        float r = xs[i] - __bfloat162float(h0);
        __nv_bfloat16 h1 = __float2bfloat16(r);
        a |= (unsigned long long)__bfloat16_as_ushort(h0) << (16 * i);
        b |= (unsigned long long)__bfloat16_as_ushort(h1) << (16 * i);
    }
    p0 = a; p1 = b;
}

// fused select + gather + bf16 split emission: one warp per final position
__global__ void k_selgather(const float* __restrict__ X, const int* __restrict__ T) {
    int w = (blockIdx.x * blockDim.x + threadIdx.x) >> 5;
    int lane = threadIdx.x & 31;
    if (w >= N_SEL) return;
    unsigned q = g_qsel[w];

    int lo = 0, hi = NBUCK - 1;
    while (lo < hi) {
        int mid = (lo + hi + 1) >> 1;
        if (g_start[mid] <= q) lo = mid; else hi = mid - 1;
    }
    unsigned r = q - g_start[lo];
    unsigned n = min(g_cnt[lo], (unsigned)BCAP);

    unsigned ke = 0xFFFFFFFFu, ve = 0xFFFFFFFFu;
    if (lane < (int)n) { ke = g_keyB[lo * BCAP + lane]; ve = g_valB[lo * BCAP + lane]; }
    unsigned rank = 0;
    for (unsigned f = 0; f < n; f++) {
        unsigned kf = __shfl_sync(0xffffffffu, ke, f);
        unsigned vf = __shfl_sync(0xffffffffu, ve, f);
        if (lane < (int)n && (kf < ke || (kf == ke && vf < ve))) rank++;
    }
    unsigned m = __ballot_sync(0xffffffffu, lane < (int)n && rank == r);
    unsigned src = __shfl_sync(0xffffffffu, ve, __ffs(m) - 1);

    const float4* xr = (const float4*)(X + (size_t)src * DIMS);
    float4 v0 = xr[lane], v1 = xr[lane + 32];
    unsigned long long p0, p1;
    bf16_split4(v0, p0, p1);
    *(unsigned long long*)(g_Xb0 + (size_t)w * DIMS + lane * 4) = p0;
    *(unsigned long long*)(g_Xb1 + (size_t)w * DIMS + lane * 4) = p1;
    bf16_split4(v1, p0, p1);
    *(unsigned long long*)(g_Xb0 + (size_t)w * DIMS + 128 + lane * 4) = p0;
    *(unsigned long long*)(g_Xb1 + (size_t)w * DIMS + 128 + lane * 4) = p1;

    float ss = v0.x * v0.x + v0.y * v0.y + v0.z * v0.z + v0.w * v0.w
             + v1.x * v1.x + v1.y * v1.y + v1.z * v1.z + v1.w * v1.w;
#pragma unroll
    for (int o = 16; o > 0; o >>= 1) ss += __shfl_xor_sync(0xffffffffu, ss, o);
    if (lane == 0) { g_sq[w] = ss; g_lab[w] = T[src]; }
}

// ---------------- mma.sync bf16x2 split-GEMM main (exact R12 body, no tail) ----------
// 680 symmetric CTAs, 128 threads (2x2 warps, 32x32 warp tiles), K-chunks of 128
// smem: A0,A1,B0,B1 (64 rows x 128 bf16 = 16KB each) + sq/lab = 66560 B -> 3 CTAs/SM
#define TILE_B   16384
#define SM_SQA   (4 * TILE_B)
#define SM_SQB   (SM_SQA + 256)
#define SM_LABA  (SM_SQB + 256)
#define SM_LABB  (SM_LABA + 256)
#define SMEM_MAIN (SM_LABB + 256)

__global__ void __launch_bounds__(128, 3) k_main() {
    extern __shared__ char sm[];
    const unsigned base = smem_u32(sm);
    float* sqA = (float*)(sm + SM_SQA);
    float* sqB = (float*)(sm + SM_SQB);
    int* labA = (int*)(sm + SM_LABA);
    int* labB = (int*)(sm + SM_LABB);

    const int tid = threadIdx.x;
    const int lane = tid & 31, wid = tid >> 5;
    const int wrow = (wid >> 1) * 32, wcol = (wid & 1) * 32;

    const int u = blockIdx.x;
    int blk = u / 136;
    int sidx = u - blk * 136;
    int rt = 0, rem = sidx;
    while (rem >= 16 - rt) { rem -= 16 - rt; rt++; }
    int ct = rt + rem;
    const int r0 = rt * 64, c0 = ct * 64;
    const int nrows = min(64, BATCH - r0);
    const int ncols = min(64, BATCH - c0);
    const int rowBase = blk * BATCH + r0;
    const int colBase = blk * BATCH + c0;

    if (tid < 64) {
        sqA[tid]  = (tid < nrows) ? g_sq[rowBase + tid] : 0.f;
        labA[tid] = (tid < nrows) ? g_lab[rowBase + tid] : -1;
        sqB[tid]  = (tid < ncols) ? g_sq[colBase + tid] : 0.f;
        labB[tid] = (tid < ncols) ? g_lab[colBase + tid] : -2;
    }

    float acc[2][4][4];
#pragma unroll
    for (int mi = 0; mi < 2; mi++)
#pragma unroll
        for (int ni = 0; ni < 4; ni++)
#pragma unroll
            for (int e = 0; e < 4; e++) acc[mi][ni][e] = 0.f;

    const int rowA = wrow + (lane & 15);
    const int rowB = wcol + (lane & 7) + ((lane & 16) ? 8 : 0);
    const int chA = (lane >> 4);
    const int chB = ((lane >> 3) & 1);

    for (int ch = 0; ch < 2; ch++) {
        __syncthreads();
        // load 4 tiles (16B chunk per thread-iter), XOR swizzle: chunk16 ^= row&7
        for (int i = tid; i < 64 * 16; i += 128) {
            int r = i >> 4, c = i & 15;
            unsigned dsto = (unsigned)(r * 256 + ((c ^ (r & 7)) << 4));
            uint4 z = make_uint4(0, 0, 0, 0);
            uint4 a0 = z, a1 = z, b0 = z, b1 = z;
            if (r < nrows) {
                size_t goff = (size_t)(rowBase + r) * DIMS + ch * 128 + c * 8;
                a0 = *(const uint4*)(g_Xb0 + goff);
                a1 = *(const uint4*)(g_Xb1 + goff);
            }
            if (r < ncols) {
                size_t goff = (size_t)(colBase + r) * DIMS + ch * 128 + c * 8;
                b0 = *(const uint4*)(g_Xb0 + goff);
                b1 = *(const uint4*)(g_Xb1 + goff);
            }
            *(uint4*)(sm + 0 * TILE_B + dsto) = a0;
            *(uint4*)(sm + 1 * TILE_B + dsto) = a1;
            *(uint4*)(sm + 2 * TILE_B + dsto) = b0;
            *(uint4*)(sm + 3 * TILE_B + dsto) = b1;
        }
        __syncthreads();

#pragma unroll 1
        for (int seg = 0; seg < 3; seg++) {
            const unsigned aTile = base + ((seg == 1) ? 1u : 0u) * TILE_B;
            const unsigned bTile = base + ((seg == 2) ? 3u : 2u) * TILE_B;
#pragma unroll
            for (int s = 0; s < 8; s++) {
                unsigned af[2][4], bf[2][4];
#pragma unroll
                for (int mi = 0; mi < 2; mi++) {
                    int rA = rowA + mi * 16;
                    unsigned addr = aTile + rA * 256 + ((((2 * s) + chA) ^ (rA & 7)) << 4);
                    ldm_x4(af[mi][0], af[mi][1], af[mi][2], af[mi][3], addr);
                }
#pragma unroll
                for (int nj = 0; nj < 2; nj++) {
                    int rB = rowB + nj * 16;
                    unsigned addr = bTile + rB * 256 + ((((2 * s) + chB) ^ (rB & 7)) << 4);
                    ldm_x4(bf[nj][0], bf[nj][1], bf[nj][2], bf[nj][3], addr);
                }
#pragma unroll
                for (int mi = 0; mi < 2; mi++) {
#pragma unroll
                    for (int nj = 0; nj < 2; nj++) {
                        mma_bf16(acc[mi][2 * nj],     af[mi], &bf[nj][0]);
                        mma_bf16(acc[mi][2 * nj + 1], af[mi], &bf[nj][2]);
                    }
                }
            }
        }
    }

    // ---- epilogue on d^2 ----
    const int g = lane >> 2, qd = lane & 3;
    const float INF = __uint_as_float(0x7f800000u);
    float rP[4], rN[4], cP[8], cN[8];
#pragma unroll
    for (int i = 0; i < 4; i++) { rP[i] = 0.f; rN[i] = INF; }
#pragma unroll
    for (int j = 0; j < 8; j++) { cP[j] = 0.f; cN[j] = INF; }

#pragma unroll
    for (int mi = 0; mi < 2; mi++) {
#pragma unroll
        for (int half = 0; half < 2; half++) {
            int row = wrow + mi * 16 + g + half * 8;
            float sqi = sqA[row];
            int   li  = labA[row];
            bool  vr  = row < nrows;
            int   ri  = mi * 2 + half;
#pragma unroll
            for (int ni = 0; ni < 4; ni++) {
#pragma unroll
                for (int par = 0; par < 2; par++) {
                    int col = wcol + ni * 8 + 2 * qd + par;
                    float gg = acc[mi][ni][half * 2 + par];
                    if (vr && col < ncols) {
                        float d2 = fmaxf(sqi + sqB[col] - 2.f * gg, 1e-12f);
                        int ci = ni * 2 + par;
                        if (li == labB[col]) { rP[ri] = fmaxf(rP[ri], d2); cP[ci] = fmaxf(cP[ci], d2); }
                        else                 { rN[ri] = fminf(rN[ri], d2); cN[ci] = fminf(cN[ci], d2); }
                    }
                }
            }
        }
    }
#pragma unroll
    for (int o = 1; o < 4; o <<= 1) {
#pragma unroll
        for (int i = 0; i < 4; i++) {
            rP[i] = fmaxf(rP[i], __shfl_xor_sync(0xffffffffu, rP[i], o));
            rN[i] = fminf(rN[i], __shfl_xor_sync(0xffffffffu, rN[i], o));
        }
    }
#pragma unroll
    for (int o = 4; o < 32; o <<= 1) {
#pragma unroll
        for (int j = 0; j < 8; j++) {
            cP[j] = fmaxf(cP[j], __shfl_xor_sync(0xffffffffu, cP[j], o));
            cN[j] = fminf(cN[j], __shfl_xor_sync(0xffffffffu, cN[j], o));
        }
    }
    if (qd == 0) {
#pragma unroll
        for (int i = 0; i < 4; i++) {
            int row = wrow + (i >> 1) * 16 + g + (i & 1) * 8;
            if (row < nrows) {
                if (rP[i] > 0.f) atomicMax(&g_ap[rowBase + row], __float_as_uint(rP[i]));
                if (__float_as_uint(rN[i]) != 0x7f800000u)
                    atomicMin(&g_an[rowBase + row], __float_as_uint(rN[i]));
            }
        }
    }
    if (g == 0) {
#pragma unroll
        for (int j = 0; j < 8; j++) {
            int col = wcol + (j >> 1) * 8 + 2 * qd + (j & 1);
            if (col < ncols) {
                if (cP[j] > 0.f) atomicMax(&g_ap[colBase + col], __float_as_uint(cP[j]));
                if (__float_as_uint(cN[j]) != 0x7f800000u)
                    atomicMin(&g_an[colBase + col], __float_as_uint(cN[j]));
            }
        }
    }
}

__global__ void k_reduce(float* __restrict__ out) {
    __shared__ float s[1024];
    int t = threadIdx.x;
    float acc = 0.f;
    for (int i = t; i < N_SEL; i += 1024) {
        float ap = sqrtf(__uint_as_float(g_ap[i]));
        float an = sqrtf(__uint_as_float(g_an[i]));
        acc += fmaxf(ap - an + 0.5f, 0.f);
    }
    s[t] = acc;
    __syncthreads();
    for (int off = 512; off > 0; off >>= 1) {
        if (t < off) s[t] += s[t + off];
        __syncthreads();
    }
    if (t == 0) out[0] = s[0] * (1.0f / (float)BATCH);
}

// ---------------- launch ----------------
extern "C" void kernel_launch(void* const* d_in, const int* in_sizes, int n_in,
                              void* d_out, int out_size) {
    const float* X  = (const float*)d_in[0];
    const int*   T  = (const int*)d_in[1];
    const int*   UU = (const int*)d_in[2];
    float* out = (float*)d_out;
    (void)in_sizes; (void)n_in; (void)out_size;

    const int SMEM_SR = CAP * 8;   // 64 KB (rank block)

    cudaFuncSetAttribute(k_scanrank, cudaFuncAttributeMaxDynamicSharedMemorySize, SMEM_SR);
    cudaFuncSetAttribute(k_main,     cudaFuncAttributeMaxDynamicSharedMemorySize, SMEM_MAIN);

    k_keysinit<<<KEYS_BLOCKS, 256>>>(UU);
    k_scanrank<<<65, 1024, SMEM_SR>>>();
    k_selgather<<<(N_SEL * 32 + 127) / 128, 128>>>(X, T);
    k_main<<<NUNITS, 128, SMEM_MAIN>>>();
    k_reduce<<<1, 1024>>>(out);
}